// round 8
// baseline (speedup 1.0000x reference)
#include <cuda_runtime.h>

#define TS   32
#define HALO 6
#define LW   44          // halo rows
#define LP   52          // padded lum row stride (floats); 48 cols used
#define N_PIX 87040

struct SMem {
    float lum[LW * LP];        // 44 rows x 48 used cols (pixel p -> col p+8)
    float hT [TS * LW];        // H-blurred, TRANSPOSED: [col*44 + row]
    float inv[TS * (TS + 1)];  // per-pixel 1/denominator (stride 33)
    float sx [TS];
    float sy [TS];
};

// 16-window (phase 3a): element m (0..15) -> output j, tap T[|m-6-j|] if <=6
#define CONTRIB2(vv, m)                                             \
    { if ((m) <= 12)              o0 += T[(m) >= 6 ? (m)-6 : 6-(m)] * (vv); \
      if ((m) >= 1 && (m) <= 13)  o1 += T[(m) >= 7 ? (m)-7 : 7-(m)] * (vv); \
      if ((m) >= 2 && (m) <= 14)  o2 += T[(m) >= 8 ? (m)-8 : 8-(m)] * (vv); \
      if ((m) >= 3)               o3 += T[(m) >= 9 ? (m)-9 : 9-(m)] * (vv); }

// 20-window (phase 2, center 8): element m (0..19) -> output j, tap T[|m-8-j|] if <=6
#define CONTRIB5(vv, m)                                             \
    { if ((m) >= 2 && (m) <= 14)  o0 += T[(m) >= 8  ? (m)-8  : 8-(m)]  * (vv); \
      if ((m) >= 3 && (m) <= 15)  o1 += T[(m) >= 9  ? (m)-9  : 9-(m)]  * (vv); \
      if ((m) >= 4 && (m) <= 16)  o2 += T[(m) >= 10 ? (m)-10 : 10-(m)] * (vv); \
      if ((m) >= 5 && (m) <= 17)  o3 += T[(m) >= 11 ? (m)-11 : 11-(m)] * (vv); }

template<int W>
__device__ __forceinline__ void run_tile(int tloc, const float* __restrict__ base,
                                         float* __restrict__ obase, SMem& sm, int tid)
{
    const float T[7] = { 1.0f, 0.94595947f, 0.80073740f, 0.60653066f,
                         0.41111229f, 0.24935220f, 0.13533528f };
    constexpr int TPR = W / TS;

    const int tx0 = (tloc & (TPR - 1)) * TS;
    const int ty0 = (tloc / TPR) * TS;

    // ---- dens tables: clipped 1-D tap sums (zero 'SAME' padding) ----
    if (tid < 64) {
        int p = tid & 31;
        int g = (tid < 32 ? tx0 : ty0) + p;
        float s = T[0];
        s += (g >= 1 ? T[1] : 0.f) + (g >= 2 ? T[2] : 0.f) + (g >= 3 ? T[3] : 0.f)
           + (g >= 4 ? T[4] : 0.f) + (g >= 5 ? T[5] : 0.f) + (g >= 6 ? T[6] : 0.f);
        int d = W - 1 - g;
        s += (d >= 1 ? T[1] : 0.f) + (d >= 2 ? T[2] : 0.f) + (d >= 3 ? T[3] : 0.f)
           + (d >= 4 ? T[4] : 0.f) + (d >= 5 ? T[5] : 0.f) + (d >= 6 ? T[6] : 0.f);
        if (tid < 32) sm.sx[p] = s; else sm.sy[p] = s;
    }

    // ---- phase 1: vectorized luminance gather ----
    // Task = 12 consecutive floats (4 RGB pixels) of one halo row.
    // Row covers pixel cols [tx0-8, tx0+40): start (tx0-8)*3 is 16B-aligned.
    // 44 rows * 12 segs = 528 tasks.
    {
        const bool interior = (W >= 128) && (tx0 >= 8) && (ty0 >= HALO) &&
                              (tx0 + 40 <= W) && (ty0 + 38 <= W);
        int r   = tid / 12;
        int seg = tid - r * 12;
        if (interior) {
            for (int t = tid; t < 528; t += 256) {
                int u = ((ty0 - 6 + r) * W + tx0 - 8) * 3 + seg * 12;
                float4 a = *(const float4*)(base + u);
                float4 b = *(const float4*)(base + u + 4);
                float4 c = *(const float4*)(base + u + 8);
                float4 o;
                o.x = 0.2989f * a.x + 0.587f * a.y + 0.114f * a.z;
                o.y = 0.2989f * a.w + 0.587f * b.x + 0.114f * b.y;
                o.z = 0.2989f * b.z + 0.587f * b.w + 0.114f * c.x;
                o.w = 0.2989f * c.y + 0.587f * c.z + 0.114f * c.w;
                *(float4*)&sm.lum[r * LP + seg * 4] = o;
                r += 21; seg += 4;
                if (seg >= 12) { seg -= 12; r += 1; }
            }
        } else {
            const int hi = 3 * W * W - 4;
            for (int t = tid; t < 528; t += 256) {
                int gy = ty0 - 6 + r;
                int gx0 = tx0 - 8 + seg * 4;
                int u = (gy * W + gx0) * 3;
                int u0 = min(max(u,     0), hi);
                int u1 = min(max(u + 4, 0), hi);
                int u2 = min(max(u + 8, 0), hi);
                float4 a = *(const float4*)(base + u0);
                float4 b = *(const float4*)(base + u1);
                float4 c = *(const float4*)(base + u2);
                bool ry = (unsigned)gy < (unsigned)W;
                float4 o;
                o.x = (ry && (unsigned)(gx0    ) < (unsigned)W) ? (0.2989f * a.x + 0.587f * a.y + 0.114f * a.z) : 0.f;
                o.y = (ry && (unsigned)(gx0 + 1) < (unsigned)W) ? (0.2989f * a.w + 0.587f * b.x + 0.114f * b.y) : 0.f;
                o.z = (ry && (unsigned)(gx0 + 2) < (unsigned)W) ? (0.2989f * b.z + 0.587f * b.w + 0.114f * c.x) : 0.f;
                o.w = (ry && (unsigned)(gx0 + 3) < (unsigned)W) ? (0.2989f * c.y + 0.587f * c.z + 0.114f * c.w) : 0.f;
                *(float4*)&sm.lum[r * LP + seg * 4] = o;
                r += 21; seg += 4;
                if (seg >= 12) { seg -= 12; r += 1; }
            }
        }
    }
    __syncthreads();

    // ---- phase 2: horizontal blur; 5 aligned LDS.128, 4 outputs; store transposed ----
    // Output pixel col 4cg+j sits at buffer col 4cg+j+8; window = buffer cols [4cg, 4cg+20)
    {
        int cg = tid / 44;           // col-group 0..7
        int r  = tid - cg * 44;      // row 0..43
        int t  = tid;
#pragma unroll
        for (int pass = 0; pass < 2; pass++) {
            if (t < 352) {
                const float* row = &sm.lum[r * LP + 4 * cg];
                float o0 = 0.f, o1 = 0.f, o2 = 0.f, o3 = 0.f;
#pragma unroll
                for (int g = 0; g < 5; g++) {
                    float4 q = *(const float4*)(row + 4 * g);
                    CONTRIB5(q.x, 4 * g + 0);
                    CONTRIB5(q.y, 4 * g + 1);
                    CONTRIB5(q.z, 4 * g + 2);
                    CONTRIB5(q.w, 4 * g + 3);
                }
                float* dst = &sm.hT[(4 * cg) * 44 + r];
                dst[0]   = o0;
                dst[44]  = o1;
                dst[88]  = o2;
                dst[132] = o3;
            }
            t += 256;
            cg += 5;
            r  += 36;
            if (r >= 44) { r -= 44; cg += 1; }
        }
    }
    __syncthreads();

    // ---- phase 3a: vertical blur (4 rows/thread) via LDS.128 + dens ----
    {
        const int c  = tid & 31;
        const int r0 = (tid >> 5) << 2;
        const float* colp = &sm.hT[c * 44 + r0];   // 16B-aligned
        float a[16];
#pragma unroll
        for (int m = 0; m < 16; m++) a[m] = colp[m];

        float o0 = 0.f, o1 = 0.f, o2 = 0.f, o3 = 0.f;
#pragma unroll
        for (int m = 0; m < 16; m++) { CONTRIB2(a[m], m); }

        const float sx = sm.sx[c];
        float* invp = &sm.inv[r0 * 33 + c];
        { float dens = 0.9999f * sm.sy[r0 + 0] * sx; invp[0]  = __fdividef(dens, o0 + 1e-3f * dens); }
        { float dens = 0.9999f * sm.sy[r0 + 1] * sx; invp[33] = __fdividef(dens, o1 + 1e-3f * dens); }
        { float dens = 0.9999f * sm.sy[r0 + 2] * sx; invp[66] = __fdividef(dens, o2 + 1e-3f * dens); }
        { float dens = 0.9999f * sm.sy[r0 + 3] * sx; invp[99] = __fdividef(dens, o3 + 1e-3f * dens); }
    }
    __syncthreads();

    // ---- phase 3b: vectorized I/O; 32 rows x 24 float4 = 768 = 3*256 tasks ----
    {
        int row = (tid * 21846) >> 19;   // tid/24 (exact for tid<768)
        int f   = tid - row * 24;
#pragma unroll
        for (int it = 0; it < 3; it++) {
            int u   = f << 2;                 // first float in row (0..92)
            int p0  = (u * 21846) >> 16;      // u/3
            int fm3 = u - 3 * p0;
            int th  = 3 - fm3;

            const float* invrow = &sm.inv[row * 33];
            float iA = invrow[p0];
            float iB = invrow[p0 + 1];

            int goff = ((ty0 + row) * W + tx0) * 3 + u;
            float4 q = *(const float4*)(base + goff);
            q.x *= iA;
            q.y *= (1 < th) ? iA : iB;
            q.z *= (2 < th) ? iA : iB;
            q.w *= iB;
            *(float4*)(obase + goff) = q;

            row += 10;
            f   += 16;
            if (f >= 24) { f -= 24; row += 1; }
        }
    }
}

__global__ __launch_bounds__(256, 8)
void lln_kernel(const float* __restrict__ x, float* __restrict__ out)
{
    __shared__ SMem sm;
    const int tile = blockIdx.x;
    const int b    = blockIdx.y;
    const int tid  = threadIdx.x;
    const int bo   = b * (N_PIX * 3);

    if (tile < 64) {
        run_tile<256>(tile,      x + bo,              out + bo,              sm, tid);
    } else if (tile < 80) {
        run_tile<128>(tile - 64, x + bo + 65536 * 3,  out + bo + 65536 * 3,  sm, tid);
    } else if (tile < 84) {
        run_tile<64> (tile - 80, x + bo + 81920 * 3,  out + bo + 81920 * 3,  sm, tid);
    } else {
        run_tile<32> (0,         x + bo + 86016 * 3,  out + bo + 86016 * 3,  sm, tid);
    }
}

extern "C" void kernel_launch(void* const* d_in, const int* in_sizes, int n_in,
                              void* d_out, int out_size)
{
    const float* x = (const float*)d_in[0];
    float* out     = (float*)d_out;
    dim3 grid(85, 128);
    lln_kernel<<<grid, 256>>>(x, out);
}

// round 10
// speedup vs baseline: 1.1430x; 1.1430x over previous
#include <cuda_runtime.h>

#define N_PIX 87040

// ---- shared pool (worst case TS=64): lum 76*84 + hT 64*76 + sx64 + sy64 ----
#define POOL_FLOATS (76 * 84 + 64 * 76 + 128)

// 24-float window (phase 2): element m (0..23) -> output j (0..7), tap T[|m-8-j|] if <=6
#define CONTRIB8(vv, m)                                                          \
    { if ((m) >= 2  && (m) <= 14) o0 += T[(m) >= 8  ? (m)-8  : 8-(m)]  * (vv);   \
      if ((m) >= 3  && (m) <= 15) o1 += T[(m) >= 9  ? (m)-9  : 9-(m)]  * (vv);   \
      if ((m) >= 4  && (m) <= 16) o2 += T[(m) >= 10 ? (m)-10 : 10-(m)] * (vv);   \
      if ((m) >= 5  && (m) <= 17) o3 += T[(m) >= 11 ? (m)-11 : 11-(m)] * (vv);   \
      if ((m) >= 6  && (m) <= 18) o4 += T[(m) >= 12 ? (m)-12 : 12-(m)] * (vv);   \
      if ((m) >= 7  && (m) <= 19) o5 += T[(m) >= 13 ? (m)-13 : 13-(m)] * (vv);   \
      if ((m) >= 8  && (m) <= 20) o6 += T[(m) >= 14 ? (m)-14 : 14-(m)] * (vv);   \
      if ((m) >= 9  && (m) <= 21) o7 += T[(m) >= 15 ? (m)-15 : 15-(m)] * (vv); }

// 16-float window (phase 3a): element m (0..15) -> output j (0..3), tap T[|m-6-j|] if <=6
#define CONTRIB4(vv, m)                                                      \
    { if ((m) <= 12)              o0 += T[(m) >= 6 ? (m)-6 : 6-(m)] * (vv);  \
      if ((m) >= 1 && (m) <= 13)  o1 += T[(m) >= 7 ? (m)-7 : 7-(m)] * (vv);  \
      if ((m) >= 2 && (m) <= 14)  o2 += T[(m) >= 8 ? (m)-8 : 8-(m)] * (vv);  \
      if ((m) >= 3)               o3 += T[(m) >= 9 ? (m)-9 : 9-(m)] * (vv); }

// W = image width (=height), TS = tile size. Compile-time only.
template<int W, int TS>
__device__ __forceinline__ void run_tile(int tloc, const float* __restrict__ base,
                                         float* __restrict__ obase,
                                         float* __restrict__ pool, int tid)
{
    const float T[7] = { 1.0f, 0.94595947f, 0.80073740f, 0.60653066f,
                         0.41111229f, 0.24935220f, 0.13533528f };
    constexpr int TPR  = W / TS;           // tiles per row
    constexpr int LR   = TS + 12;          // lum rows (halo +-6)
    constexpr int LC   = TS + 16;          // lum cols used (px -8 .. TS+7)
    constexpr int LPAD = (TS == 64) ? 84 : 52;  // padded lum row stride
    constexpr int NQ   = LC / 4;           // float4 per lum row

    float* lum = pool;                       // [LR][LPAD]
    float* hT  = pool + LR * LPAD;           // [TS][LR] transposed H-blur
    float* sxs = pool + LR * LPAD + TS * LR;
    float* sys = sxs + TS;
    float* inv = pool;                       // aliases lum (dead after P2): [TS][TS+1]

    const int tx0 = (tloc & (TPR - 1)) * TS;
    const int ty0 = (tloc / TPR) * TS;

    // ---- dens tables ----
    if (tid < 2 * TS) {
        int p = tid & (TS - 1);
        int g = (tid < TS ? tx0 : ty0) + p;
        float s = T[0];
        s += (g >= 1 ? T[1] : 0.f) + (g >= 2 ? T[2] : 0.f) + (g >= 3 ? T[3] : 0.f)
           + (g >= 4 ? T[4] : 0.f) + (g >= 5 ? T[5] : 0.f) + (g >= 6 ? T[6] : 0.f);
        int d = W - 1 - g;
        s += (d >= 1 ? T[1] : 0.f) + (d >= 2 ? T[2] : 0.f) + (d >= 3 ? T[3] : 0.f)
           + (d >= 4 ? T[4] : 0.f) + (d >= 5 ? T[5] : 0.f) + (d >= 6 ? T[6] : 0.f);
        if (tid < TS) sxs[p] = s; else sys[p] = s;
    }

    // ---- phase 1: luminance gather; task = 4 pixels (3 float4), row-major ----
    // lum buffer col q*4 + j  <->  pixel col tx0 - 8 + 4q + j
    {
        constexpr int NT = LR * NQ;
        const bool interior = (tx0 >= 8) && (ty0 >= 6) &&
                              (tx0 + TS + 8 <= W) && (ty0 + TS + 6 <= W);
        int r = tid / NQ;
        int q = tid - r * NQ;
        constexpr int DR = 512 / NQ;
        constexpr int DQ = 512 - DR * NQ;
        if (interior) {
            for (int t = tid; t < NT; t += 512) {
                int u = ((ty0 - 6 + r) * W + tx0 - 8) * 3 + q * 12;
                float4 a = *(const float4*)(base + u);
                float4 b = *(const float4*)(base + u + 4);
                float4 c = *(const float4*)(base + u + 8);
                float4 o;
                o.x = 0.2989f * a.x + 0.587f * a.y + 0.114f * a.z;
                o.y = 0.2989f * a.w + 0.587f * b.x + 0.114f * b.y;
                o.z = 0.2989f * b.z + 0.587f * b.w + 0.114f * c.x;
                o.w = 0.2989f * c.y + 0.587f * c.z + 0.114f * c.w;
                *(float4*)&lum[r * LPAD + q * 4] = o;
                q += DQ; r += DR;
                if (q >= NQ) { q -= NQ; r += 1; }
            }
        } else {
            constexpr int HI = 3 * W * W - 4;
            for (int t = tid; t < NT; t += 512) {
                int gy  = ty0 - 6 + r;
                int gx0 = tx0 - 8 + q * 4;
                int u = (gy * W + gx0) * 3;
                int u0 = min(max(u,     0), HI);
                int u1 = min(max(u + 4, 0), HI);
                int u2 = min(max(u + 8, 0), HI);
                float4 a = *(const float4*)(base + u0);
                float4 b = *(const float4*)(base + u1);
                float4 c = *(const float4*)(base + u2);
                bool ry = (unsigned)gy < (unsigned)W;
                float4 o;
                o.x = (ry && (unsigned)(gx0    ) < (unsigned)W) ? (0.2989f * a.x + 0.587f * a.y + 0.114f * a.z) : 0.f;
                o.y = (ry && (unsigned)(gx0 + 1) < (unsigned)W) ? (0.2989f * a.w + 0.587f * b.x + 0.114f * b.y) : 0.f;
                o.z = (ry && (unsigned)(gx0 + 2) < (unsigned)W) ? (0.2989f * b.z + 0.587f * b.w + 0.114f * c.x) : 0.f;
                o.w = (ry && (unsigned)(gx0 + 3) < (unsigned)W) ? (0.2989f * c.y + 0.587f * c.z + 0.114f * c.w) : 0.f;
                *(float4*)&lum[r * LPAD + q * 4] = o;
                q += DQ; r += DR;
                if (q >= NQ) { q -= NQ; r += 1; }
            }
        }
    }
    __syncthreads();

    // ---- phase 2: horizontal blur; 8 outputs/thread via 6 aligned LDS.128 ----
    // outputs px cols 8g..8g+7 need buffer cols 8g+2..8g+21  (subset of [8g, 8g+24))
    {
        constexpr int NG = TS / 8;
        constexpr int NT = NG * LR;
        for (int t = tid; t < NT; t += 512) {
            int g = t / LR;
            int r = t - g * LR;
            const float* row = &lum[r * LPAD + g * 8];
            float o0 = 0.f, o1 = 0.f, o2 = 0.f, o3 = 0.f;
            float o4 = 0.f, o5 = 0.f, o6 = 0.f, o7 = 0.f;
#pragma unroll
            for (int k = 0; k < 6; k++) {
                float4 qv = *(const float4*)(row + 4 * k);
                CONTRIB8(qv.x, 4 * k + 0);
                CONTRIB8(qv.y, 4 * k + 1);
                CONTRIB8(qv.z, 4 * k + 2);
                CONTRIB8(qv.w, 4 * k + 3);
            }
            float* dst = &hT[(g * 8) * LR + r];   // transposed
            dst[0 * LR] = o0; dst[1 * LR] = o1; dst[2 * LR] = o2; dst[3 * LR] = o3;
            dst[4 * LR] = o4; dst[5 * LR] = o5; dst[6 * LR] = o6; dst[7 * LR] = o7;
        }
    }
    __syncthreads();

    // ---- phase 3a: vertical blur, 4 rows/thread via 4 LDS.128; dens; inv -> pool ----
    {
        constexpr int NT = TS * (TS / 4);
        for (int t = tid; t < NT; t += 512) {
            int c  = t & (TS - 1);
            int r0 = (t / TS) << 2;
            const float* colp = &hT[c * LR + r0];   // LR mult of 4 -> 16B aligned
            float o0 = 0.f, o1 = 0.f, o2 = 0.f, o3 = 0.f;
#pragma unroll
            for (int k = 0; k < 4; k++) {
                float4 qv = *(const float4*)(colp + 4 * k);
                CONTRIB4(qv.x, 4 * k + 0);
                CONTRIB4(qv.y, 4 * k + 1);
                CONTRIB4(qv.z, 4 * k + 2);
                CONTRIB4(qv.w, 4 * k + 3);
            }
            const float sx = sxs[c];
            float* invp = &inv[r0 * (TS + 1) + c];
            float a0 = 0.9999f * sys[r0 + 0] * sx;
            float a1 = 0.9999f * sys[r0 + 1] * sx;
            float a2 = 0.9999f * sys[r0 + 2] * sx;
            float a3 = 0.9999f * sys[r0 + 3] * sx;
            invp[0 * (TS + 1)] = __fdividef(a0, o0 + 1e-3f * a0);
            invp[1 * (TS + 1)] = __fdividef(a1, o1 + 1e-3f * a1);
            invp[2 * (TS + 1)] = __fdividef(a2, o2 + 1e-3f * a2);
            invp[3 * (TS + 1)] = __fdividef(a3, o3 + 1e-3f * a3);
        }
    }
    __syncthreads();

    // ---- phase 3b: vectorized divide; TS rows x (TS*3/4) float4 ----
    {
        constexpr int FPR = TS * 3 / 4;       // float4 per tile row (48 or 24)
        constexpr int NT  = TS * FPR;
        for (int t = tid; t < NT; t += 512) {
            int row = (TS == 64) ? (((t >> 4) * 21846) >> 16)    // t/48
                                 : (((t >> 3) * 21846) >> 16);   // t/24
            int f   = t - row * FPR;
            int u   = f << 2;
            int p0  = (u * 21846) >> 16;      // u/3 (exact, u <= 188)
            int fm3 = u - 3 * p0;
            int th  = 3 - fm3;

            const float* invrow = &inv[row * (TS + 1)];
            float iA = invrow[p0];
            float iB = invrow[p0 + 1];

            int goff = ((ty0 + row) * W + tx0) * 3 + u;
            float4 qv = *(const float4*)(base + goff);
            qv.x *= iA;
            qv.y *= (1 < th) ? iA : iB;
            qv.z *= (2 < th) ? iA : iB;
            qv.w *= iB;
            *(float4*)(obase + goff) = qv;
        }
    }
}

__global__ __launch_bounds__(512, 4)
void lln_kernel(const float* __restrict__ x, float* __restrict__ out)
{
    __shared__ float pool[POOL_FLOATS];
    const int tile = blockIdx.x;   // 0..21
    const int b    = blockIdx.y;
    const int tid  = threadIdx.x;
    const int bo   = b * (N_PIX * 3);

    if (tile < 16) {
        run_tile<256, 64>(tile,      x + bo,             out + bo,             pool, tid);
    } else if (tile < 20) {
        run_tile<128, 64>(tile - 16, x + bo + 65536 * 3, out + bo + 65536 * 3, pool, tid);
    } else if (tile == 20) {
        run_tile<64, 64> (0,         x + bo + 81920 * 3, out + bo + 81920 * 3, pool, tid);
    } else {
        run_tile<32, 32> (0,         x + bo + 86016 * 3, out + bo + 86016 * 3, pool, tid);
    }
}

extern "C" void kernel_launch(void* const* d_in, const int* in_sizes, int n_in,
                              void* d_out, int out_size)
{
    const float* x = (const float*)d_in[0];
    float* out     = (float*)d_out;
    dim3 grid(22, 128);
    lln_kernel<<<grid, 512>>>(x, out);
}